// round 7
// baseline (speedup 1.0000x reference)
#include <cuda_runtime.h>
#include <cstdint>

#define FULLMASK 0xFFFFFFFFu
typedef unsigned long long ull;

constexpr int BATCH = 256;
constexpr int HID   = 16;
// 2*log2(e): folded into all weights/biases so tanh(a) = 1 - 2/(1+exp2(a'))
#define TANH_SCALE 2.885390081777927f

// ---- packed f32x2 helpers (Blackwell FFMA2 — only reachable via PTX) ----
__device__ __forceinline__ ull pack2(float lo, float hi) {
    ull r; asm("mov.b64 %0, {%1,%2};" : "=l"(r) : "f"(lo), "f"(hi)); return r;
}
__device__ __forceinline__ void unpack2(ull v, float& lo, float& hi) {
    asm("mov.b64 {%0,%1}, %2;" : "=f"(lo), "=f"(hi) : "l"(v));
}
__device__ __forceinline__ ull fma2(ull a, ull b, ull c) {
    ull d; asm("fma.rn.f32x2 %0, %1, %2, %3;" : "=l"(d) : "l"(a), "l"(b), "l"(c)); return d;
}
__device__ __forceinline__ ull add2(ull a, ull b) {
    ull d; asm("add.rn.f32x2 %0, %1, %2;" : "=l"(d) : "l"(a), "l"(b)); return d;
}

// tanh on a PRE-SCALED argument a' = 2*log2(e)*a:  tanh = 1 - 2/(1+exp2(a'))
__device__ __forceinline__ float tanh_pre(float a) {
    float e; asm("ex2.approx.f32 %0, %1;" : "=f"(e) : "f"(a));
    float r; asm("rcp.approx.f32 %0, %1;" : "=f"(r) : "f"(e + 1.0f));
    return fmaf(-2.0f, r, 1.0f);
}

__global__ void __launch_bounds__(32, 1) rnn3_scan_kernel(
    const float* __restrict__ x,        // [B, T, 1]
    const float* __restrict__ prev_h0,  // [2, 16]
    const float* __restrict__ post_h0,  // [1, 1]
    const float* __restrict__ W_ih0,    // [16, 1]
    const float* __restrict__ W_hh0,    // [16, 16]
    const float* __restrict__ b_ih0,    // [16]
    const float* __restrict__ b_hh0,    // [16]
    const float* __restrict__ W_ih1,    // [16, 16]
    const float* __restrict__ W_hh1,    // [16, 16]
    const float* __restrict__ b_ih1,    // [16]
    const float* __restrict__ b_hh1,    // [16]
    const float* __restrict__ W_ihp,    // [1, 16]
    const float* __restrict__ W_hhp,    // [1, 1]
    const float* __restrict__ b_ihp,    // [1]
    const float* __restrict__ b_hhp,    // [1]
    float* __restrict__ out,            // [B, T, 1]
    int T)
{
    const int lane = threadIdx.x;       // 0..31
    const int j    = lane & 15;         // hidden unit owned by this lane
    const int half = lane >> 4;         // 0 = batch A, 1 = batch B
    const int base = lane & 16;         // shfl source base for this half
    const int batch = blockIdx.x * 2 + half;

    // h1 broadcast: two-slot smem (WAR distance 2) + __syncwarp (drains STS,
    // proven fastest in R4). h0 broadcast: register shuffles (lower latency,
    // MIO pipe) — h0 is the tight self-recurrence so its chain matters most.
    __shared__ __align__(16) float SH1[2][2][16];

    const float C = TANH_SCALE;

    // ---- register-resident, pre-scaled, pair-packed weights ----
    ull whh0p[8], wih1p[8], whh1p[8];
#pragma unroll
    for (int k = 0; k < 8; k++) {
        whh0p[k] = pack2(C * __ldg(&W_hh0[j * HID + 2 * k]), C * __ldg(&W_hh0[j * HID + 2 * k + 1]));
        wih1p[k] = pack2(C * __ldg(&W_ih1[j * HID + 2 * k]), C * __ldg(&W_ih1[j * HID + 2 * k + 1]));
        whh1p[k] = pack2(C * __ldg(&W_hh1[j * HID + 2 * k]), C * __ldg(&W_hh1[j * HID + 2 * k + 1]));
    }
    const float wih0C = C * __ldg(&W_ih0[j]);
    const float bh0C  = C * (__ldg(&b_ih0[j]) + __ldg(&b_hh0[j]));
    const float bh1C  = C * (__ldg(&b_ih1[j]) + __ldg(&b_hh1[j]));
    const float wihpC = C * __ldg(&W_ihp[j]);      // own column (butterfly post dot)
    const float whhpC = C * __ldg(&W_hhp[0]);
    const float bpC   = C * (__ldg(&b_ihp[0]) + __ldg(&b_hhp[0]));

    // min-max normalize folded: xn=(x+1)/2 -> wih0C*xn + bh0C = wih0h*x + bh0h
    const float wih0h = 0.5f * wih0C;
    const float bh0h  = bh0C + wih0h;
    const ull bias1_2 = pack2(bh1C, 0.0f);

    // ---- pipeline state entering iter i:
    //   h0p = h0[i-1] (shfl-packed), h1p = h1[i-2] (smem-packed),
    //   h1d1 = own-lane h1[i-2], y = y[i-3]
    ull h0p[8], h1p[8];
#pragma unroll
    for (int k = 0; k < 8; k++) {
        h0p[k] = pack2(__ldg(&prev_h0[2 * k]),       __ldg(&prev_h0[2 * k + 1]));
        h1p[k] = pack2(__ldg(&prev_h0[HID + 2 * k]), __ldg(&prev_h0[HID + 2 * k + 1]));
    }
    float h1d1 = __ldg(&prev_h0[HID + j]);
    float y    = __ldg(&post_h0[0]);

    const float* xb = x   + (size_t)batch * T;
    float*       ob = out + (size_t)batch * T;

    // ---- stage helpers ----
    auto sdot_tanh = [&](ull xb2) -> float {           // layer 0: reads h0p; x-term at head
        ull s0 = fma2(whh0p[0], h0p[0], xb2);
        ull s1 = fma2(whh0p[4], h0p[4], 0ULL);
#pragma unroll
        for (int k = 1; k < 4; k++) {
            s0 = fma2(whh0p[k],     h0p[k],     s0);
            s1 = fma2(whh0p[4 + k], h0p[4 + k], s1);
        }
        ull ss = add2(s0, s1);
        float lo, hi; unpack2(ss, lo, hi);
        return tanh_pre(lo + hi);
    };
    auto tdot_tanh = [&]() -> float {                   // layer 1: reads h0p, h1p (4 chains of 4)
        ull t0 = fma2(wih1p[0], h0p[0], bias1_2);
        ull t1 = fma2(wih1p[4], h0p[4], 0ULL);
        ull t2 = fma2(whh1p[0], h1p[0], 0ULL);
        ull t3 = fma2(whh1p[4], h1p[4], 0ULL);
#pragma unroll
        for (int k = 1; k < 4; k++) {
            t0 = fma2(wih1p[k],     h0p[k],     t0);
            t1 = fma2(wih1p[4 + k], h0p[4 + k], t1);
            t2 = fma2(whh1p[k],     h1p[k],     t2);
            t3 = fma2(whh1p[4 + k], h1p[4 + k], t3);
        }
        ull tt = add2(add2(t0, t1), add2(t2, t3));
        float lo, hi; unpack2(tt, lo, hi);
        return tanh_pre(lo + hi);
    };
    auto pdot_tanh = [&]() -> float {                   // post: butterfly on own h1[i-2] (MIO pipe)
        float pr = wihpC * h1d1;
        pr += __shfl_xor_sync(FULLMASK, pr, 1);
        pr += __shfl_xor_sync(FULLMASK, pr, 2);
        pr += __shfl_xor_sync(FULLMASK, pr, 4);
        pr += __shfl_xor_sync(FULLMASK, pr, 8);
        return tanh_pre(pr + fmaf(whhpC, y, bpC));
    };
    auto bcast0 = [&](float h0n) {                      // h0 broadcast via shuffles
#pragma unroll
        for (int k = 0; k < 8; k++)
            h0p[k] = pack2(__shfl_sync(FULLMASK, h0n, base + 2 * k),
                           __shfl_sync(FULLMASK, h0n, base + 2 * k + 1));
    };
    auto ldp1 = [&](const float* bsrc) {                // h1 broadcast load (4x LDS.128)
        const ulonglong2* p = (const ulonglong2*)bsrc;
        ulonglong2 a = p[0], b = p[1], c = p[2], d = p[3];
        h1p[0] = a.x; h1p[1] = a.y; h1p[2] = b.x; h1p[3] = b.y;
        h1p[4] = c.x; h1p[5] = c.y; h1p[6] = d.x; h1p[7] = d.y;
    };

    float yq0 = 0.f, yq1 = 0.f, yq2 = 0.f, yq3 = 0.f;

    // ---- prologue: i = 0..3 (pipeline fill + alignment peel) ----
    {
        const float4 x03 = *(const float4*)xb;   // x[0..3]
        {   // i = 0: h0[0]
            float h0n = sdot_tanh(pack2(fmaf(wih0h, x03.x, bh0h), 0.0f));
            bcast0(h0n);
        }
        {   // i = 1: h0[1], h1[0]
            ull xb2 = pack2(fmaf(wih0h, x03.y, bh0h), 0.0f);
            float h0n = sdot_tanh(xb2);
            float h1n = tdot_tanh();
            SH1[1][half][j] = h1n;
            bcast0(h0n);
            __syncwarp();
            ldp1(SH1[1][half]);
            h1d1 = h1n;
        }
        {   // i = 2: h0[2], h1[1], y[0]
            ull xb2 = pack2(fmaf(wih0h, x03.z, bh0h), 0.0f);
            float h0n = sdot_tanh(xb2);
            float h1n = tdot_tanh();
            float yn  = pdot_tanh();
            SH1[0][half][j] = h1n;
            bcast0(h0n);
            __syncwarp();
            ldp1(SH1[0][half]);
            h1d1 = h1n;
            y = yn; yq0 = yn;
        }
        {   // i = 3: h0[3], h1[2], y[1]
            ull xb2 = pack2(fmaf(wih0h, x03.w, bh0h), 0.0f);
            float h0n = sdot_tanh(xb2);
            float h1n = tdot_tanh();
            float yn  = pdot_tanh();
            SH1[1][half][j] = h1n;
            bcast0(h0n);
            __syncwarp();
            ldp1(SH1[1][half]);
            h1d1 = h1n;
            y = yn; yq1 = yn;
        }
    }

    // ---- x prefetch: aligned float4, 2-deep ----
    const float4* X = (const float4*)xb;
    float4 xcur = X[1];                       // x[4..7]
    float4 xnxt = X[2];                       // x[8..11]

    // ---- main loop: tc = 4 .. T-4 step 4; iter i = tc+s computes h0[i], h1[i-1], y[i-2] ----
    for (int tc = 4; tc < T; tc += 4) {
#pragma unroll
        for (int s = 0; s < 4; s++) {
            const int slot = s & 1;           // tc is even
            const float xt = (s == 0) ? xcur.x : (s == 1) ? xcur.y : (s == 2) ? xcur.z : xcur.w;
            const ull xb2 = pack2(fmaf(wih0h, xt, bh0h), 0.0f);   // off-chain (x prefetched)

            // Three stage dots read only OLD state -> mutually independent.
            float h0n = sdot_tanh(xb2);       // -> h0[i]
            float h1n = tdot_tanh();          // -> h1[i-1]
            float yn  = pdot_tanh();          // -> y[i-2]  (butterfly, MIO pipe)

            SH1[slot][half][j] = h1n;         // h1 smem broadcast (slack >= 1 iter)
            bcast0(h0n);                      // h0 register broadcast (chain-critical)
            __syncwarp();                     // drains STS -> clean LDS (R4 evidence)
            ldp1(SH1[slot][half]);
            h1d1 = h1n;
            y = yn;

            // y[i-2] lands at queue position (s+2)&3
            if (s == 0) yq2 = yn;
            else if (s == 1) {
                yq3 = yn;
                if (j == 0) *(float4*)(ob + tc - 4) = make_float4(yq0, yq1, yq2, yq3);
            }
            else if (s == 2) yq0 = yn;
            else yq1 = yn;
        }
        xcur = xnxt;
        xnxt = (tc + 8 < T) ? X[tc / 4 + 2] : xnxt;
    }

    // ---- epilogue: i = T (h1[T-1], y[T-2]), i = T+1 (y[T-1]) ----
    {
        float h1n = tdot_tanh();   // h1[T-1]  (h0p=h0[T-1], h1p=h1[T-2])
        float yn  = pdot_tanh();   // y[T-2]   (h1d1=h1[T-2], y=y[T-3])
        h1d1 = h1n;
        y = yn; yq2 = yn;
    }
    {
        float yn = pdot_tanh();    // y[T-1]
        yq3 = yn;
        if (j == 0) *(float4*)(ob + T - 4) = make_float4(yq0, yq1, yq2, yq3);
    }
}

extern "C" void kernel_launch(void* const* d_in, const int* in_sizes, int n_in,
                              void* d_out, int out_size)
{
    const float* x       = (const float*)d_in[0];
    const float* prev_h0 = (const float*)d_in[1];
    const float* post_h0 = (const float*)d_in[2];
    const float* W_ih0   = (const float*)d_in[3];
    const float* W_hh0   = (const float*)d_in[4];
    const float* b_ih0   = (const float*)d_in[5];
    const float* b_hh0   = (const float*)d_in[6];
    const float* W_ih1   = (const float*)d_in[7];
    const float* W_hh1   = (const float*)d_in[8];
    const float* b_ih1   = (const float*)d_in[9];
    const float* b_hh1   = (const float*)d_in[10];
    const float* W_ihp   = (const float*)d_in[11];
    const float* W_hhp   = (const float*)d_in[12];
    const float* b_ihp   = (const float*)d_in[13];
    const float* b_hhp   = (const float*)d_in[14];
    float* out = (float*)d_out;

    const int T = in_sizes[0] / BATCH;   // IN == 1, T = 16384 (multiple of 4)

    rnn3_scan_kernel<<<BATCH / 2, 32>>>(
        x, prev_h0, post_h0,
        W_ih0, W_hh0, b_ih0, b_hh0,
        W_ih1, W_hh1, b_ih1, b_hh1,
        W_ihp, W_hhp, b_ihp, b_hhp,
        out, T);
}